// round 15
// baseline (speedup 1.0000x reference)
#include <cuda_runtime.h>
#include <cuda_fp16.h>
#include <cstdint>
#include <math.h>

typedef unsigned int u32;

#define B_ROWS 16384
#define HID    512
#define IN     256
#define KCAT   256   // pure fp16 GEMM
#define NCAT   1024  // [Wre rows | Wim rows]
#define NCHUNK 4
#define MCH    (B_ROWS / NCHUNK)          // 4096 rows per chunk

#define PAD(i) ((i) + ((i) >> 3))

// ---------------- scratch ---------------------------------------------------
__device__ __half g_xcat[(size_t)B_ROWS * KCAT];
__device__ __half g_wcat[(size_t)NCAT * KCAT];
__device__ float  g_embP[(size_t)B_ROWS * NCAT];  // planar per row: [re(512) | im(512)]
__device__ float2 g_d1n[HID];
__device__ float2 g_v1p[HID];
__device__ float2 g_d2r8[HID];
__device__ float2 g_d3[HID];
__device__ float2 g_v2[HID];
__device__ int    g_pp8[HID];
__device__ float2 g_twf[HID];
__device__ float2 g_twi[HID];

// ---------------- helpers ---------------------------------------------------
__device__ __forceinline__ float2 cmul(float2 a, float2 b) {
    return make_float2(fmaf(a.x, b.x, -a.y * b.y), fmaf(a.x, b.y, a.y * b.x));
}
__device__ __forceinline__ float2 cadd(float2 a, float2 b) {
    return make_float2(a.x + b.x, a.y + b.y);
}
__device__ __forceinline__ float2 csub(float2 a, float2 b) {
    return make_float2(a.x - b.x, a.y - b.y);
}

template <int SIGN>
__device__ __forceinline__ void dft8(float2 x[8]) {
    const float S = 0.70710678118654752440f;
    float2 a0 = cadd(x[0], x[4]), b0 = csub(x[0], x[4]);
    float2 a1 = cadd(x[1], x[5]), b1 = csub(x[1], x[5]);
    float2 a2 = cadd(x[2], x[6]), b2 = csub(x[2], x[6]);
    float2 a3 = cadd(x[3], x[7]), b3 = csub(x[3], x[7]);
    b1 = cmul(b1, make_float2(S, SIGN * S));
    b2 = (SIGN < 0) ? make_float2(b2.y, -b2.x) : make_float2(-b2.y, b2.x);
    b3 = cmul(b3, make_float2(-S, SIGN * S));
    float2 c0 = cadd(a0, a2), c1 = csub(a0, a2);
    float2 c2 = cadd(a1, a3), c3 = csub(a1, a3);
    c3 = (SIGN < 0) ? make_float2(c3.y, -c3.x) : make_float2(-c3.y, c3.x);
    x[0] = cadd(c0, c2); x[4] = csub(c0, c2);
    x[2] = cadd(c1, c3); x[6] = csub(c1, c3);
    float2 d0 = cadd(b0, b2), d1 = csub(b0, b2);
    float2 d2 = cadd(b1, b3), d3 = csub(b1, b3);
    d3 = (SIGN < 0) ? make_float2(d3.y, -d3.x) : make_float2(-d3.y, d3.x);
    x[1] = cadd(d0, d2); x[5] = csub(d0, d2);
    x[3] = cadd(d1, d3); x[7] = csub(d1, d3);
}

template <int SIGN>
__device__ __forceinline__ void fft_stage1(float2* b, int t,
                                           const float2* __restrict__ tw) {
    int j = t & 7, g = t >> 3;
    int base = (g << 6) + j;
    float2 x[8];
    #pragma unroll
    for (int k = 0; k < 8; k++) x[k] = b[PAD(base + (k << 3))];
    #pragma unroll
    for (int k = 1; k < 8; k++) x[k] = cmul(x[k], tw[(j * k) << 3]);
    dft8<SIGN>(x);
    #pragma unroll
    for (int k = 0; k < 8; k++) b[PAD(base + (k << 3))] = x[k];
}

// ---------------- prep -------------------------------------------------------
__global__ void prep_kernel(const float* __restrict__ angles,
                            const float* __restrict__ rre,
                            const float* __restrict__ rim,
                            const int*   __restrict__ perm) {
    int t = threadIdx.x;  // 512 threads
    float a1 = rre[t],       b1 = rim[t];
    float a2 = rre[512 + t], b2 = rim[512 + t];
    float p = a1 * a1 + b1 * b1;
    float q = a2 * a2 + b2 * b2;
    #pragma unroll
    for (int o = 16; o; o >>= 1) {
        p += __shfl_xor_sync(0xffffffffu, p, o);
        q += __shfl_xor_sync(0xffffffffu, q, o);
    }
    __shared__ float sp[16], sq[16];
    __shared__ float fn1, fn2;
    int w = t >> 5, lane = t & 31;
    if (!lane) { sp[w] = p; sq[w] = q; }
    __syncthreads();
    if (t == 0) {
        float P = 0.f, Q = 0.f;
        for (int i = 0; i < 16; i++) { P += sp[i]; Q += sq[i]; }
        fn1 = 1.f / (sqrtf(P) + 1e-8f);
        fn2 = 1.f / (sqrtf(Q) + 1e-8f);
    }
    __syncthreads();
    int F = (t & 0x1C0) | ((t & 7) << 3) | ((t >> 3) & 7);
    g_v1p[F] = make_float2(a1 * fn1, b1 * fn1);
    g_v2[t]  = make_float2(a2 * fn2, b2 * fn2);

    int r8 = ((t & 7) << 6) | (t & 56) | (t >> 6);
    float s, c;
    __sincosf(angles[t], &s, &c);          g_d1n[t]   = make_float2(c, s);
    __sincosf(angles[512 + t], &s, &c);    g_d2r8[r8] = make_float2(c, s);
    __sincosf(angles[1024 + t], &s, &c);   g_d3[t]    = make_float2(c, s);
    g_pp8[r8] = PAD(perm[t]);

    {
        double ang = -2.0 * 3.14159265358979323846 * (double)t / 512.0;
        float cc = (float)cos(ang), ss = (float)sin(ang);
        g_twf[t] = make_float2(cc, ss);
        g_twi[t] = make_float2(cc, -ss);
    }
}

// ---------------- fp16 conversion (vectorized) --------------------------------
__device__ __forceinline__ u32 pack2h(float a, float b) {
    __half2 h = __floats2half2_rn(a, b);
    return *(u32*)&h;
}

__global__ void convert_x_kernel(const float* __restrict__ x) {
    int i4 = blockIdx.x * 256 + threadIdx.x;
    float4 v = ((const float4*)x)[i4];
    uint2 o;
    o.x = pack2h(v.x, v.y);
    o.y = pack2h(v.z, v.w);
    ((uint2*)g_xcat)[i4] = o;
}

__global__ void convert_w_kernel(const float* __restrict__ Wre,
                                 const float* __restrict__ Wim) {
    int i4 = blockIdx.x * 256 + threadIdx.x;
    int h = i4 >> 6;
    int cq = i4 & 63;
    const float* src = (h < 512) ? (Wre + (size_t)h * 256)
                                 : (Wim + (size_t)(h - 512) * 256);
    float4 v = ((const float4*)src)[cq];
    uint2 o;
    o.x = pack2h(v.x, v.y);
    o.y = pack2h(v.z, v.w);
    ((uint2*)g_wcat)[i4] = o;
}

// ---------------- tensor-core GEMM (chunked in M) -----------------------------
#define STG  10240
#define BOFF (3 * STG)
#define NIT  (KCAT / 32)   // 8

__device__ __forceinline__ void ldsm_x4(u32 addr, u32& r0, u32& r1,
                                        u32& r2, u32& r3) {
    asm volatile("ldmatrix.sync.aligned.m8n8.x4.shared.b16 {%0,%1,%2,%3}, [%4];"
                 : "=r"(r0), "=r"(r1), "=r"(r2), "=r"(r3) : "r"(addr));
}
__device__ __forceinline__ void mma16816(float* c, const u32* a,
                                         u32 b0, u32 b1) {
    asm volatile(
        "mma.sync.aligned.m16n8k16.row.col.f32.f16.f16.f32 "
        "{%0,%1,%2,%3}, {%4,%5,%6,%7}, {%8,%9}, {%0,%1,%2,%3};"
        : "+f"(c[0]), "+f"(c[1]), "+f"(c[2]), "+f"(c[3])
        : "r"(a[0]), "r"(a[1]), "r"(a[2]), "r"(a[3]), "r"(b0), "r"(b1));
}

__global__ void __launch_bounds__(128) mma_gemm_kernel(int mOff) {
    extern __shared__ __align__(16) char dsm[];

    int tid  = threadIdx.x;
    int warp = tid >> 5, lane = tid & 31;
    int bm = (blockIdx.y + mOff) << 7, bn = blockIdx.x << 7;
    int wm = (warp & 1) << 6, wn = (warp >> 1) << 6;

    u32 sBase = (u32)__cvta_generic_to_shared(dsm);

    int lr = tid >> 2, lc = (tid & 3) << 3;
    const __half* gA = g_xcat + (size_t)(bm + lr) * KCAT + lc;
    const __half* gB = g_wcat + (size_t)(bn + lr) * KCAT + lc;
    u32 stA = sBase + (u32)(lr * 80 + (tid & 3) * 16);
    u32 stB = stA + BOFF;

    int frow  = lane & 15;
    int fbyte = (lane >> 4) << 4;
    u32 aOff[4], bOff[4];
    #pragma unroll
    for (int i = 0; i < 4; i++)
        aOff[i] = (u32)((wm + i * 16 + frow) * 80 + fbyte);
    #pragma unroll
    for (int j = 0; j < 4; j++)
        bOff[j] = (u32)(BOFF + (wn + j * 16 + frow) * 80 + fbyte);

    float c[4][8][4];
    #pragma unroll
    for (int i = 0; i < 4; i++)
        #pragma unroll
        for (int o = 0; o < 8; o++)
            #pragma unroll
            for (int k = 0; k < 4; k++) c[i][o][k] = 0.f;

    #pragma unroll
    for (int st = 0; st < 2; st++) {
        u32 offs = st * STG;
        int k = st * 32;
        #pragma unroll
        for (int p = 0; p < 4; p++) {
            asm volatile("cp.async.cg.shared.global [%0], [%1], 16;" ::
                "r"(stA + offs + p * 32 * 80), "l"(gA + (size_t)p * 32 * KCAT + k));
            asm volatile("cp.async.cg.shared.global [%0], [%1], 16;" ::
                "r"(stB + offs + p * 32 * 80), "l"(gB + (size_t)p * 32 * KCAT + k));
        }
        asm volatile("cp.async.commit_group;");
    }

    #pragma unroll 1
    for (int it = 0; it < NIT; it++) {
        asm volatile("cp.async.wait_group 1;");
        __syncthreads();
        if (it + 2 < NIT) {
            int st = (it + 2) % 3;
            u32 offs = (u32)(st * STG);
            int k = (it + 2) * 32;
            #pragma unroll
            for (int p = 0; p < 4; p++) {
                asm volatile("cp.async.cg.shared.global [%0], [%1], 16;" ::
                    "r"(stA + offs + p * 32 * 80), "l"(gA + (size_t)p * 32 * KCAT + k));
                asm volatile("cp.async.cg.shared.global [%0], [%1], 16;" ::
                    "r"(stB + offs + p * 32 * 80), "l"(gB + (size_t)p * 32 * KCAT + k));
            }
        }
        asm volatile("cp.async.commit_group;");

        u32 so = sBase + (u32)((it % 3) * STG);
        #pragma unroll
        for (int kk = 0; kk < 2; kk++) {
            u32 a[4][4], b[4][4];
            #pragma unroll
            for (int i = 0; i < 4; i++)
                ldsm_x4(so + aOff[i] + kk * 32, a[i][0], a[i][1], a[i][2], a[i][3]);
            #pragma unroll
            for (int j = 0; j < 4; j++)
                ldsm_x4(so + bOff[j] + kk * 32, b[j][0], b[j][1], b[j][2], b[j][3]);
            #pragma unroll
            for (int i = 0; i < 4; i++)
                #pragma unroll
                for (int o = 0; o < 8; o++) {
                    int t = o >> 1, p = o & 1;
                    mma16816(c[i][o], a[i], b[t][p], b[t][p + 2]);
                }
        }
    }

    int g = lane >> 2, tg = lane & 3;
    #pragma unroll
    for (int i = 0; i < 4; i++) {
        int r0 = bm + wm + i * 16 + g;
        #pragma unroll
        for (int o = 0; o < 8; o++) {
            int cc = bn + wn + o * 8 + tg * 2;
            *(float2*)(g_embP + (size_t)r0 * NCAT + cc)       = make_float2(c[i][o][0], c[i][o][1]);
            *(float2*)(g_embP + (size_t)(r0 + 8) * NCAT + cc) = make_float2(c[i][o][2], c[i][o][3]);
        }
    }
}

// ---------------- urnn: DIF forward + DIT inverse, fused tail, chunked -------
__global__ void __launch_bounds__(256) urnn_kernel(const float* __restrict__ hxr,
                                                   const float* __restrict__ hxi,
                                                   const float* __restrict__ beta,
                                                   float2* __restrict__ out,
                                                   int bOff) {
    __shared__ float2 buf[4][576];
    __shared__ float2 sred[8];

    int tid = threadIdx.x;
    int sub = tid >> 6;
    int t   = tid & 63;
    int warp = tid >> 5;
    int row = ((blockIdx.x + bOff) << 2) + sub;
    size_t base = (size_t)row * HID;

    float2* b = buf[sub];
    float2 x[8];

    // ===== forward FFT (DIF radix-8) =====
    #pragma unroll
    for (int m = 0; m < 8; m++) {
        int i = t + (m << 6);
        x[m] = cmul(g_d1n[i], make_float2(hxr[base + i], hxi[base + i]));
    }
    dft8<-1>(x);
    #pragma unroll
    for (int m = 1; m < 8; m++) x[m] = cmul(x[m], g_twf[t * m]);
    #pragma unroll
    for (int m = 0; m < 8; m++) b[PAD((m << 6) + t)] = x[m];
    __syncthreads();

    {
        int m2 = t >> 3, a = t & 7;
        #pragma unroll
        for (int bb = 0; bb < 8; bb++) x[bb] = b[PAD((m2 << 6) + (bb << 3) + a)];
        dft8<-1>(x);
        #pragma unroll
        for (int d = 1; d < 8; d++) x[d] = cmul(x[d], g_twf[(a * d) << 3]);
        #pragma unroll
        for (int d = 0; d < 8; d++) b[PAD((m2 << 6) + (d << 3) + a)] = x[d];
    }
    __syncthreads();

    #pragma unroll
    for (int a = 0; a < 8; a++) x[a] = b[PAD((t << 3) + a)];
    dft8<-1>(x);

    // Householder 1
    float2 v[8];
    float2 acc = make_float2(0.f, 0.f);
    #pragma unroll
    for (int c = 0; c < 8; c++) {
        v[c] = g_v1p[(c << 6) + t];
        acc = cadd(acc, cmul(x[c], v[c]));
    }
    #pragma unroll
    for (int o = 16; o; o >>= 1) {
        acc.x += __shfl_xor_sync(0xffffffffu, acc.x, o);
        acc.y += __shfl_xor_sync(0xffffffffu, acc.y, o);
    }
    if ((tid & 31) == 0) sred[warp] = acc;
    __syncthreads();
    {
        float2 s = cadd(sred[sub << 1], sred[(sub << 1) | 1]);
        float2 m = make_float2(2.f * s.x, 2.f * s.y);
        #pragma unroll
        for (int c = 0; c < 8; c++)
            x[c] = csub(x[c], cmul(m, make_float2(v[c].x, -v[c].y)));
    }
    __syncthreads();
    {
        int lo = ((t & 7) << 3) + (t >> 3);
        #pragma unroll
        for (int c = 0; c < 8; c++) b[PAD((c << 6) + lo)] = x[c];
    }
    __syncthreads();

    // ===== inverse FFT (DIT) =====
    #pragma unroll
    for (int k = 0; k < 8; k++) {
        int i = (t << 3) + k;
        x[k] = cmul(g_d2r8[i], b[g_pp8[i]]);
    }
    dft8<1>(x);
    __syncthreads();
    #pragma unroll
    for (int k = 0; k < 8; k++) b[PAD((t << 3) + k)] = x[k];
    __syncthreads();

    fft_stage1<1>(b, t, g_twi);
    __syncthreads();

    #pragma unroll
    for (int k = 0; k < 8; k++) x[k] = b[PAD(t + (k << 6))];
    #pragma unroll
    for (int k = 1; k < 8; k++) x[k] = cmul(x[k], g_twi[t * k]);
    dft8<1>(x);

    const float inv = 1.f / 512.f;
    #pragma unroll
    for (int k = 0; k < 8; k++) { x[k].x *= inv; x[k].y *= inv; }

    // Householder 2
    acc = make_float2(0.f, 0.f);
    #pragma unroll
    for (int k = 0; k < 8; k++) {
        v[k] = g_v2[t + (k << 6)];
        acc = cadd(acc, cmul(x[k], v[k]));
    }
    #pragma unroll
    for (int o = 16; o; o >>= 1) {
        acc.x += __shfl_xor_sync(0xffffffffu, acc.x, o);
        acc.y += __shfl_xor_sync(0xffffffffu, acc.y, o);
    }
    if ((tid & 31) == 0) sred[warp] = acc;
    __syncthreads();
    float2 s2 = cadd(sred[sub << 1], sred[(sub << 1) | 1]);
    float2 m2 = make_float2(2.f * s2.x, 2.f * s2.y);

    const float* embRe = g_embP + (size_t)row * NCAT;
    const float* embIm = embRe + 512;

    #pragma unroll
    for (int k = 0; k < 8; k++) {
        int e = t + (k << 6);
        float2 h = csub(x[k], cmul(m2, make_float2(v[k].x, -v[k].y)));
        h = cmul(g_d3[e], h);
        h.x += embRe[e]; h.y += embIm[e];
        float d = h.x * h.x + h.y * h.y;
        float2 res;
        if (d > 0.f) {
            float rs  = rsqrtf(d);
            float mag = d * rs;
            float r   = mag + beta[e];
            r = r > 0.f ? r : 0.f;
            float sc = r * rs;
            res = make_float2(sc * h.x, sc * h.y);
        } else {
            float r = beta[e] > 0.f ? beta[e] : 0.f;
            res = make_float2(r, 0.f);
        }
        out[base + e] = res;
    }
}

// ---------------- launch -----------------------------------------------------
extern "C" void kernel_launch(void* const* d_in, const int* in_sizes, int n_in,
                              void* d_out, int out_size) {
    const float* x      = (const float*)d_in[0];
    const float* hxr    = (const float*)d_in[1];
    const float* hxi    = (const float*)d_in[2];
    const float* angles = (const float*)d_in[3];
    const float* rre    = (const float*)d_in[4];
    const float* rim    = (const float*)d_in[5];
    const float* Wre    = (const float*)d_in[6];
    const float* Wim    = (const float*)d_in[7];
    const float* beta   = (const float*)d_in[8];
    const int*   perm   = (const int*)d_in[9];
    float2* out = (float2*)d_out;

    static cudaStream_t s2 = 0;
    static cudaEvent_t ev0 = 0;
    static cudaEvent_t evG[NCHUNK] = {0, 0, 0, 0};
    static int inited = 0;
    if (!inited) {
        cudaFuncSetAttribute(mma_gemm_kernel,
                             cudaFuncAttributeMaxDynamicSharedMemorySize, 6 * STG);
        cudaStreamCreateWithFlags(&s2, cudaStreamNonBlocking);
        cudaEventCreateWithFlags(&ev0, cudaEventDisableTiming);
        for (int c = 0; c < NCHUNK; c++)
            cudaEventCreateWithFlags(&evG[c], cudaEventDisableTiming);
        inited = 1;
    }

    // fork: converts + chunked GEMM on s2
    cudaEventRecord(ev0, 0);
    cudaStreamWaitEvent(s2, ev0, 0);
    convert_x_kernel<<<B_ROWS * IN / 4 / 256, 256, 0, s2>>>(x);
    convert_w_kernel<<<NCAT * IN / 4 / 256, 256, 0, s2>>>(Wre, Wim);
    for (int c = 0; c < NCHUNK; c++) {
        dim3 gg(NCAT / 128, MCH / 128);
        mma_gemm_kernel<<<gg, 128, 6 * STG, s2>>>(c * (MCH / 128));
        cudaEventRecord(evG[c], s2);
    }

    // main stream: prep, then chunked urnn pipelined against the GEMM chunks
    prep_kernel<<<1, 512>>>(angles, rre, rim, perm);
    for (int c = 0; c < NCHUNK; c++) {
        cudaStreamWaitEvent(0, evG[c], 0);
        urnn_kernel<<<MCH / 4, 256>>>(hxr, hxi, beta, out, c * (MCH / 4));
    }
}

// round 16
// speedup vs baseline: 1.1614x; 1.1614x over previous
#include <cuda_runtime.h>
#include <cuda_fp16.h>
#include <cstdint>
#include <math.h>

typedef unsigned int u32;

#define B_ROWS 16384
#define HID    512
#define IN     256
#define KCAT   256   // pure fp16 GEMM
#define NCAT   1024  // [Wre rows | Wim rows]

#define PAD(i) ((i) + ((i) >> 3))

// ---------------- scratch ---------------------------------------------------
__device__ __half g_xcat[(size_t)B_ROWS * KCAT];
__device__ __half g_wcat[(size_t)NCAT * KCAT];
__device__ float  g_embP[(size_t)B_ROWS * NCAT];  // planar per row: [re(512) | im(512)]
__device__ float2 g_d1n[HID];
__device__ float2 g_v1p[HID];
__device__ float2 g_d2r8[HID];
__device__ float2 g_d3[HID];
__device__ float2 g_v2[HID];
__device__ int    g_pp8[HID];
__device__ float2 g_twf[HID];
__device__ float2 g_twi[HID];

// ---------------- helpers ---------------------------------------------------
__device__ __forceinline__ float2 cmul(float2 a, float2 b) {
    return make_float2(fmaf(a.x, b.x, -a.y * b.y), fmaf(a.x, b.y, a.y * b.x));
}
__device__ __forceinline__ float2 cadd(float2 a, float2 b) {
    return make_float2(a.x + b.x, a.y + b.y);
}
__device__ __forceinline__ float2 csub(float2 a, float2 b) {
    return make_float2(a.x - b.x, a.y - b.y);
}

template <int SIGN>
__device__ __forceinline__ void dft8(float2 x[8]) {
    const float S = 0.70710678118654752440f;
    float2 a0 = cadd(x[0], x[4]), b0 = csub(x[0], x[4]);
    float2 a1 = cadd(x[1], x[5]), b1 = csub(x[1], x[5]);
    float2 a2 = cadd(x[2], x[6]), b2 = csub(x[2], x[6]);
    float2 a3 = cadd(x[3], x[7]), b3 = csub(x[3], x[7]);
    b1 = cmul(b1, make_float2(S, SIGN * S));
    b2 = (SIGN < 0) ? make_float2(b2.y, -b2.x) : make_float2(-b2.y, b2.x);
    b3 = cmul(b3, make_float2(-S, SIGN * S));
    float2 c0 = cadd(a0, a2), c1 = csub(a0, a2);
    float2 c2 = cadd(a1, a3), c3 = csub(a1, a3);
    c3 = (SIGN < 0) ? make_float2(c3.y, -c3.x) : make_float2(-c3.y, c3.x);
    x[0] = cadd(c0, c2); x[4] = csub(c0, c2);
    x[2] = cadd(c1, c3); x[6] = csub(c1, c3);
    float2 d0 = cadd(b0, b2), d1 = csub(b0, b2);
    float2 d2 = cadd(b1, b3), d3 = csub(b1, b3);
    d3 = (SIGN < 0) ? make_float2(d3.y, -d3.x) : make_float2(-d3.y, d3.x);
    x[1] = cadd(d0, d2); x[5] = csub(d0, d2);
    x[3] = cadd(d1, d3); x[7] = csub(d1, d3);
}

template <int SIGN>
__device__ __forceinline__ void fft_stage1(float2* b, int t,
                                           const float2* __restrict__ tw) {
    int j = t & 7, g = t >> 3;
    int base = (g << 6) + j;
    float2 x[8];
    #pragma unroll
    for (int k = 0; k < 8; k++) x[k] = b[PAD(base + (k << 3))];
    #pragma unroll
    for (int k = 1; k < 8; k++) x[k] = cmul(x[k], tw[(j * k) << 3]);
    dft8<SIGN>(x);
    #pragma unroll
    for (int k = 0; k < 8; k++) b[PAD(base + (k << 3))] = x[k];
}

// ---------------- prep -------------------------------------------------------
__global__ void prep_kernel(const float* __restrict__ angles,
                            const float* __restrict__ rre,
                            const float* __restrict__ rim,
                            const int*   __restrict__ perm) {
    int t = threadIdx.x;  // 512 threads
    float a1 = rre[t],       b1 = rim[t];
    float a2 = rre[512 + t], b2 = rim[512 + t];
    float p = a1 * a1 + b1 * b1;
    float q = a2 * a2 + b2 * b2;
    #pragma unroll
    for (int o = 16; o; o >>= 1) {
        p += __shfl_xor_sync(0xffffffffu, p, o);
        q += __shfl_xor_sync(0xffffffffu, q, o);
    }
    __shared__ float sp[16], sq[16];
    __shared__ float fn1, fn2;
    int w = t >> 5, lane = t & 31;
    if (!lane) { sp[w] = p; sq[w] = q; }
    __syncthreads();
    if (t == 0) {
        float P = 0.f, Q = 0.f;
        for (int i = 0; i < 16; i++) { P += sp[i]; Q += sq[i]; }
        fn1 = 1.f / (sqrtf(P) + 1e-8f);
        fn2 = 1.f / (sqrtf(Q) + 1e-8f);
    }
    __syncthreads();
    int F = (t & 0x1C0) | ((t & 7) << 3) | ((t >> 3) & 7);
    g_v1p[F] = make_float2(a1 * fn1, b1 * fn1);
    g_v2[t]  = make_float2(a2 * fn2, b2 * fn2);

    int r8 = ((t & 7) << 6) | (t & 56) | (t >> 6);
    float s, c;
    __sincosf(angles[t], &s, &c);          g_d1n[t]   = make_float2(c, s);
    __sincosf(angles[512 + t], &s, &c);    g_d2r8[r8] = make_float2(c, s);
    __sincosf(angles[1024 + t], &s, &c);   g_d3[t]    = make_float2(c, s);
    g_pp8[r8] = PAD(perm[t]);

    {
        double ang = -2.0 * 3.14159265358979323846 * (double)t / 512.0;
        float cc = (float)cos(ang), ss = (float)sin(ang);
        g_twf[t] = make_float2(cc, ss);
        g_twi[t] = make_float2(cc, -ss);
    }
}

// ---------------- fp16 conversion (vectorized) --------------------------------
__device__ __forceinline__ u32 pack2h(float a, float b) {
    __half2 h = __floats2half2_rn(a, b);
    return *(u32*)&h;
}

__global__ void convert_x_kernel(const float* __restrict__ x) {
    int i4 = blockIdx.x * 256 + threadIdx.x;
    float4 v = ((const float4*)x)[i4];
    uint2 o;
    o.x = pack2h(v.x, v.y);
    o.y = pack2h(v.z, v.w);
    ((uint2*)g_xcat)[i4] = o;
}

__global__ void convert_w_kernel(const float* __restrict__ Wre,
                                 const float* __restrict__ Wim) {
    int i4 = blockIdx.x * 256 + threadIdx.x;
    int h = i4 >> 6;
    int cq = i4 & 63;
    const float* src = (h < 512) ? (Wre + (size_t)h * 256)
                                 : (Wim + (size_t)(h - 512) * 256);
    float4 v = ((const float4*)src)[cq];
    uint2 o;
    o.x = pack2h(v.x, v.y);
    o.y = pack2h(v.z, v.w);
    ((uint2*)g_wcat)[i4] = o;
}

// ---------------- tensor-core GEMM (monolithic, R14) --------------------------
#define STG  10240
#define BOFF (3 * STG)
#define NIT  (KCAT / 32)   // 8

__device__ __forceinline__ void ldsm_x4(u32 addr, u32& r0, u32& r1,
                                        u32& r2, u32& r3) {
    asm volatile("ldmatrix.sync.aligned.m8n8.x4.shared.b16 {%0,%1,%2,%3}, [%4];"
                 : "=r"(r0), "=r"(r1), "=r"(r2), "=r"(r3) : "r"(addr));
}
__device__ __forceinline__ void mma16816(float* c, const u32* a,
                                         u32 b0, u32 b1) {
    asm volatile(
        "mma.sync.aligned.m16n8k16.row.col.f32.f16.f16.f32 "
        "{%0,%1,%2,%3}, {%4,%5,%6,%7}, {%8,%9}, {%0,%1,%2,%3};"
        : "+f"(c[0]), "+f"(c[1]), "+f"(c[2]), "+f"(c[3])
        : "r"(a[0]), "r"(a[1]), "r"(a[2]), "r"(a[3]), "r"(b0), "r"(b1));
}

__global__ void __launch_bounds__(128) mma_gemm_kernel() {
    extern __shared__ __align__(16) char dsm[];

    int tid  = threadIdx.x;
    int warp = tid >> 5, lane = tid & 31;
    int bm = blockIdx.y << 7, bn = blockIdx.x << 7;
    int wm = (warp & 1) << 6, wn = (warp >> 1) << 6;

    u32 sBase = (u32)__cvta_generic_to_shared(dsm);

    int lr = tid >> 2, lc = (tid & 3) << 3;
    const __half* gA = g_xcat + (size_t)(bm + lr) * KCAT + lc;
    const __half* gB = g_wcat + (size_t)(bn + lr) * KCAT + lc;
    u32 stA = sBase + (u32)(lr * 80 + (tid & 3) * 16);
    u32 stB = stA + BOFF;

    int frow  = lane & 15;
    int fbyte = (lane >> 4) << 4;
    u32 aOff[4], bOff[4];
    #pragma unroll
    for (int i = 0; i < 4; i++)
        aOff[i] = (u32)((wm + i * 16 + frow) * 80 + fbyte);
    #pragma unroll
    for (int j = 0; j < 4; j++)
        bOff[j] = (u32)(BOFF + (wn + j * 16 + frow) * 80 + fbyte);

    float c[4][8][4];
    #pragma unroll
    for (int i = 0; i < 4; i++)
        #pragma unroll
        for (int o = 0; o < 8; o++)
            #pragma unroll
            for (int k = 0; k < 4; k++) c[i][o][k] = 0.f;

    #pragma unroll
    for (int st = 0; st < 2; st++) {
        u32 offs = st * STG;
        int k = st * 32;
        #pragma unroll
        for (int p = 0; p < 4; p++) {
            asm volatile("cp.async.cg.shared.global [%0], [%1], 16;" ::
                "r"(stA + offs + p * 32 * 80), "l"(gA + (size_t)p * 32 * KCAT + k));
            asm volatile("cp.async.cg.shared.global [%0], [%1], 16;" ::
                "r"(stB + offs + p * 32 * 80), "l"(gB + (size_t)p * 32 * KCAT + k));
        }
        asm volatile("cp.async.commit_group;");
    }

    #pragma unroll 1
    for (int it = 0; it < NIT; it++) {
        asm volatile("cp.async.wait_group 1;");
        __syncthreads();
        if (it + 2 < NIT) {
            int st = (it + 2) % 3;
            u32 offs = (u32)(st * STG);
            int k = (it + 2) * 32;
            #pragma unroll
            for (int p = 0; p < 4; p++) {
                asm volatile("cp.async.cg.shared.global [%0], [%1], 16;" ::
                    "r"(stA + offs + p * 32 * 80), "l"(gA + (size_t)p * 32 * KCAT + k));
                asm volatile("cp.async.cg.shared.global [%0], [%1], 16;" ::
                    "r"(stB + offs + p * 32 * 80), "l"(gB + (size_t)p * 32 * KCAT + k));
            }
        }
        asm volatile("cp.async.commit_group;");

        u32 so = sBase + (u32)((it % 3) * STG);
        #pragma unroll
        for (int kk = 0; kk < 2; kk++) {
            u32 a[4][4], b[4][4];
            #pragma unroll
            for (int i = 0; i < 4; i++)
                ldsm_x4(so + aOff[i] + kk * 32, a[i][0], a[i][1], a[i][2], a[i][3]);
            #pragma unroll
            for (int j = 0; j < 4; j++)
                ldsm_x4(so + bOff[j] + kk * 32, b[j][0], b[j][1], b[j][2], b[j][3]);
            #pragma unroll
            for (int i = 0; i < 4; i++)
                #pragma unroll
                for (int o = 0; o < 8; o++) {
                    int t = o >> 1, p = o & 1;
                    mma16816(c[i][o], a[i], b[t][p], b[t][p + 2]);
                }
        }
    }

    int g = lane >> 2, tg = lane & 3;
    #pragma unroll
    for (int i = 0; i < 4; i++) {
        int r0 = bm + wm + i * 16 + g;
        #pragma unroll
        for (int o = 0; o < 8; o++) {
            int cc = bn + wn + o * 8 + tg * 2;
            *(float2*)(g_embP + (size_t)r0 * NCAT + cc)       = make_float2(c[i][o][0], c[i][o][1]);
            *(float2*)(g_embP + (size_t)(r0 + 8) * NCAT + cc) = make_float2(c[i][o][2], c[i][o][3]);
        }
    }
}

// ---------------- urnn: DIF fwd + DIT inv, fused tail, occupancy 5 -----------
__global__ void __launch_bounds__(256, 5) urnn_kernel(const float* __restrict__ hxr,
                                                      const float* __restrict__ hxi,
                                                      const float* __restrict__ beta,
                                                      float2* __restrict__ out) {
    __shared__ float2 buf[4][576];
    __shared__ float2 sred[8];

    int tid = threadIdx.x;
    int sub = tid >> 6;
    int t   = tid & 63;
    int warp = tid >> 5;
    int row = (blockIdx.x << 2) + sub;
    size_t base = (size_t)row * HID;

    float2* b = buf[sub];
    float2 x[8];

    // ===== forward FFT (DIF radix-8): natural input straight from gmem =====
    #pragma unroll
    for (int m = 0; m < 8; m++) {
        int i = t + (m << 6);
        x[m] = cmul(g_d1n[i], make_float2(hxr[base + i], hxi[base + i]));
    }
    dft8<-1>(x);
    #pragma unroll
    for (int m = 1; m < 8; m++) x[m] = cmul(x[m], g_twf[t * m]);
    #pragma unroll
    for (int m = 0; m < 8; m++) b[PAD((m << 6) + t)] = x[m];
    __syncthreads();

    // stage 2
    {
        int m2 = t >> 3, a = t & 7;
        #pragma unroll
        for (int bb = 0; bb < 8; bb++) x[bb] = b[PAD((m2 << 6) + (bb << 3) + a)];
        dft8<-1>(x);
        #pragma unroll
        for (int d = 1; d < 8; d++) x[d] = cmul(x[d], g_twf[(a * d) << 3]);
        #pragma unroll
        for (int d = 0; d < 8; d++) b[PAD((m2 << 6) + (d << 3) + a)] = x[d];
    }
    __syncthreads();

    // stage 3 in registers
    #pragma unroll
    for (int a = 0; a < 8; a++) x[a] = b[PAD((t << 3) + a)];
    dft8<-1>(x);

    // Householder 1
    float2 v[8];
    float2 acc = make_float2(0.f, 0.f);
    #pragma unroll
    for (int c = 0; c < 8; c++) {
        v[c] = g_v1p[(c << 6) + t];
        acc = cadd(acc, cmul(x[c], v[c]));
    }
    #pragma unroll
    for (int o = 16; o; o >>= 1) {
        acc.x += __shfl_xor_sync(0xffffffffu, acc.x, o);
        acc.y += __shfl_xor_sync(0xffffffffu, acc.y, o);
    }
    if ((tid & 31) == 0) sred[warp] = acc;
    __syncthreads();
    {
        float2 s = cadd(sred[sub << 1], sred[(sub << 1) | 1]);
        float2 m = make_float2(2.f * s.x, 2.f * s.y);
        #pragma unroll
        for (int c = 0; c < 8; c++)
            x[c] = csub(x[c], cmul(m, make_float2(v[c].x, -v[c].y)));
    }
    // safe to write b without another barrier: all reads of b (stage 3)
    // completed before the sred __syncthreads above
    {
        int lo = ((t & 7) << 3) + (t >> 3);
        #pragma unroll
        for (int c = 0; c < 8; c++) b[PAD((c << 6) + lo)] = x[c];
    }
    __syncthreads();

    // ===== inverse FFT (DIT) =====
    #pragma unroll
    for (int k = 0; k < 8; k++) {
        int i = (t << 3) + k;
        x[k] = cmul(g_d2r8[i], b[g_pp8[i]]);
    }
    dft8<1>(x);
    __syncthreads();
    #pragma unroll
    for (int k = 0; k < 8; k++) b[PAD((t << 3) + k)] = x[k];
    __syncthreads();

    fft_stage1<1>(b, t, g_twi);
    __syncthreads();

    #pragma unroll
    for (int k = 0; k < 8; k++) x[k] = b[PAD(t + (k << 6))];
    #pragma unroll
    for (int k = 1; k < 8; k++) x[k] = cmul(x[k], g_twi[t * k]);
    dft8<1>(x);

    const float inv = 1.f / 512.f;
    #pragma unroll
    for (int k = 0; k < 8; k++) { x[k].x *= inv; x[k].y *= inv; }

    // Householder 2
    acc = make_float2(0.f, 0.f);
    #pragma unroll
    for (int k = 0; k < 8; k++) {
        v[k] = g_v2[t + (k << 6)];
        acc = cadd(acc, cmul(x[k], v[k]));
    }
    #pragma unroll
    for (int o = 16; o; o >>= 1) {
        acc.x += __shfl_xor_sync(0xffffffffu, acc.x, o);
        acc.y += __shfl_xor_sync(0xffffffffu, acc.y, o);
    }
    if ((tid & 31) == 0) sred[warp] = acc;
    __syncthreads();
    float2 s2 = cadd(sred[sub << 1], sred[(sub << 1) | 1]);
    float2 m2 = make_float2(2.f * s2.x, 2.f * s2.y);

    const float* embRe = g_embP + (size_t)row * NCAT;
    const float* embIm = embRe + 512;

    #pragma unroll
    for (int k = 0; k < 8; k++) {
        int e = t + (k << 6);
        float2 h = csub(x[k], cmul(m2, make_float2(v[k].x, -v[k].y)));
        h = cmul(g_d3[e], h);
        h.x += embRe[e]; h.y += embIm[e];
        float d = h.x * h.x + h.y * h.y;
        float2 res;
        if (d > 0.f) {
            float rs  = rsqrtf(d);
            float mag = d * rs;
            float r   = mag + beta[e];
            r = r > 0.f ? r : 0.f;
            float sc = r * rs;
            res = make_float2(sc * h.x, sc * h.y);
        } else {
            float r = beta[e] > 0.f ? beta[e] : 0.f;
            res = make_float2(r, 0.f);
        }
        out[base + e] = res;
    }
}

// ---------------- launch (R14 schedule) ---------------------------------------
extern "C" void kernel_launch(void* const* d_in, const int* in_sizes, int n_in,
                              void* d_out, int out_size) {
    const float* x      = (const float*)d_in[0];
    const float* hxr    = (const float*)d_in[1];
    const float* hxi    = (const float*)d_in[2];
    const float* angles = (const float*)d_in[3];
    const float* rre    = (const float*)d_in[4];
    const float* rim    = (const float*)d_in[5];
    const float* Wre    = (const float*)d_in[6];
    const float* Wim    = (const float*)d_in[7];
    const float* beta   = (const float*)d_in[8];
    const int*   perm   = (const int*)d_in[9];
    float2* out = (float2*)d_out;

    static cudaStream_t s2 = 0;
    static cudaEvent_t ev0 = 0, evG = 0;
    static int inited = 0;
    if (!inited) {
        cudaFuncSetAttribute(mma_gemm_kernel,
                             cudaFuncAttributeMaxDynamicSharedMemorySize, 6 * STG);
        cudaStreamCreateWithFlags(&s2, cudaStreamNonBlocking);
        cudaEventCreateWithFlags(&ev0, cudaEventDisableTiming);
        cudaEventCreateWithFlags(&evG, cudaEventDisableTiming);
        inited = 1;
    }

    // fork: converts + GEMM on s2 (independent of prep)
    cudaEventRecord(ev0, 0);
    cudaStreamWaitEvent(s2, ev0, 0);
    convert_x_kernel<<<B_ROWS * IN / 4 / 256, 256, 0, s2>>>(x);
    convert_w_kernel<<<NCAT * IN / 4 / 256, 256, 0, s2>>>(Wre, Wim);
    dim3 gg(NCAT / 128, B_ROWS / 128);
    mma_gemm_kernel<<<gg, 128, 6 * STG, s2>>>();
    cudaEventRecord(evG, s2);

    // main stream: prep (tiny), then join and run urnn
    prep_kernel<<<1, 512>>>(angles, rre, rim, perm);
    cudaStreamWaitEvent(0, evG, 0);
    urnn_kernel<<<B_ROWS / 4, 256>>>(hxr, hxi, beta, out);
}

// round 17
// speedup vs baseline: 1.1936x; 1.0277x over previous
#include <cuda_runtime.h>
#include <cuda_fp16.h>
#include <cstdint>
#include <math.h>

typedef unsigned int u32;

#define B_ROWS 16384
#define HID    512
#define IN     256
#define KCAT   256   // pure fp16 GEMM
#define NCAT   1024  // [Wre rows | Wim rows]

#define PAD(i) ((i) + ((i) >> 3))

#define XQUADS (B_ROWS * IN / 4)   // 1048576
#define WQUADS (NCAT * IN / 4)     // 65536

// ---------------- scratch ---------------------------------------------------
__device__ __half g_xcat[(size_t)B_ROWS * KCAT];
__device__ __half g_wcat[(size_t)NCAT * KCAT];
__device__ float  g_embP[(size_t)B_ROWS * NCAT];  // planar per row: [re(512) | im(512)]
__device__ float2 g_d1n[HID];
__device__ float2 g_v1p[HID];
__device__ float2 g_d2r8[HID];    // (d2[rev8]) / 512  (IFFT scale folded in)
__device__ float2 g_d3[HID];
__device__ float2 g_v2[HID];
__device__ int    g_pp8[HID];
__device__ float2 g_twf[HID];
__device__ float2 g_twi[HID];

// ---------------- helpers ---------------------------------------------------
__device__ __forceinline__ float2 cmul(float2 a, float2 b) {
    return make_float2(fmaf(a.x, b.x, -a.y * b.y), fmaf(a.x, b.y, a.y * b.x));
}
__device__ __forceinline__ float2 cadd(float2 a, float2 b) {
    return make_float2(a.x + b.x, a.y + b.y);
}
__device__ __forceinline__ float2 csub(float2 a, float2 b) {
    return make_float2(a.x - b.x, a.y - b.y);
}

template <int SIGN>
__device__ __forceinline__ void dft8(float2 x[8]) {
    const float S = 0.70710678118654752440f;
    float2 a0 = cadd(x[0], x[4]), b0 = csub(x[0], x[4]);
    float2 a1 = cadd(x[1], x[5]), b1 = csub(x[1], x[5]);
    float2 a2 = cadd(x[2], x[6]), b2 = csub(x[2], x[6]);
    float2 a3 = cadd(x[3], x[7]), b3 = csub(x[3], x[7]);
    b1 = cmul(b1, make_float2(S, SIGN * S));
    b2 = (SIGN < 0) ? make_float2(b2.y, -b2.x) : make_float2(-b2.y, b2.x);
    b3 = cmul(b3, make_float2(-S, SIGN * S));
    float2 c0 = cadd(a0, a2), c1 = csub(a0, a2);
    float2 c2 = cadd(a1, a3), c3 = csub(a1, a3);
    c3 = (SIGN < 0) ? make_float2(c3.y, -c3.x) : make_float2(-c3.y, c3.x);
    x[0] = cadd(c0, c2); x[4] = csub(c0, c2);
    x[2] = cadd(c1, c3); x[6] = csub(c1, c3);
    float2 d0 = cadd(b0, b2), d1 = csub(b0, b2);
    float2 d2 = cadd(b1, b3), d3 = csub(b1, b3);
    d3 = (SIGN < 0) ? make_float2(d3.y, -d3.x) : make_float2(-d3.y, d3.x);
    x[1] = cadd(d0, d2); x[5] = csub(d0, d2);
    x[3] = cadd(d1, d3); x[7] = csub(d1, d3);
}

template <int SIGN>
__device__ __forceinline__ void fft_stage1(float2* b, int t,
                                           const float2* __restrict__ tw) {
    int j = t & 7, g = t >> 3;
    int base = (g << 6) + j;
    float2 x[8];
    #pragma unroll
    for (int k = 0; k < 8; k++) x[k] = b[PAD(base + (k << 3))];
    #pragma unroll
    for (int k = 1; k < 8; k++) x[k] = cmul(x[k], tw[(j * k) << 3]);
    dft8<SIGN>(x);
    #pragma unroll
    for (int k = 0; k < 8; k++) b[PAD(base + (k << 3))] = x[k];
}

// ---------------- prep -------------------------------------------------------
__global__ void prep_kernel(const float* __restrict__ angles,
                            const float* __restrict__ rre,
                            const float* __restrict__ rim,
                            const int*   __restrict__ perm) {
    int t = threadIdx.x;  // 512 threads
    float a1 = rre[t],       b1 = rim[t];
    float a2 = rre[512 + t], b2 = rim[512 + t];
    float p = a1 * a1 + b1 * b1;
    float q = a2 * a2 + b2 * b2;
    #pragma unroll
    for (int o = 16; o; o >>= 1) {
        p += __shfl_xor_sync(0xffffffffu, p, o);
        q += __shfl_xor_sync(0xffffffffu, q, o);
    }
    __shared__ float sp[16], sq[16];
    __shared__ float fn1, fn2;
    int w = t >> 5, lane = t & 31;
    if (!lane) { sp[w] = p; sq[w] = q; }
    __syncthreads();
    if (t == 0) {
        float P = 0.f, Q = 0.f;
        for (int i = 0; i < 16; i++) { P += sp[i]; Q += sq[i]; }
        fn1 = 1.f / (sqrtf(P) + 1e-8f);
        fn2 = 1.f / (sqrtf(Q) + 1e-8f);
    }
    __syncthreads();
    int F = (t & 0x1C0) | ((t & 7) << 3) | ((t >> 3) & 7);
    g_v1p[F] = make_float2(a1 * fn1, b1 * fn1);
    g_v2[t]  = make_float2(a2 * fn2, b2 * fn2);

    int r8 = ((t & 7) << 6) | (t & 56) | (t >> 6);
    float s, c;
    const float inv = 1.f / 512.f;
    __sincosf(angles[t], &s, &c);          g_d1n[t]   = make_float2(c, s);
    __sincosf(angles[512 + t], &s, &c);    g_d2r8[r8] = make_float2(c * inv, s * inv);
    __sincosf(angles[1024 + t], &s, &c);   g_d3[t]    = make_float2(c, s);
    g_pp8[r8] = PAD(perm[t]);

    {
        double ang = -2.0 * 3.14159265358979323846 * (double)t / 512.0;
        float cc = (float)cos(ang), ss = (float)sin(ang);
        g_twf[t] = make_float2(cc, ss);
        g_twi[t] = make_float2(cc, -ss);
    }
}

// ---------------- fp16 conversion (merged x+w, vectorized) --------------------
__device__ __forceinline__ u32 pack2h(float a, float b) {
    __half2 h = __floats2half2_rn(a, b);
    return *(u32*)&h;
}

__global__ void convert_kernel(const float* __restrict__ x,
                               const float* __restrict__ Wre,
                               const float* __restrict__ Wim) {
    int i4 = blockIdx.x * 256 + threadIdx.x;
    if (i4 < XQUADS) {
        float4 v = ((const float4*)x)[i4];
        uint2 o;
        o.x = pack2h(v.x, v.y);
        o.y = pack2h(v.z, v.w);
        ((uint2*)g_xcat)[i4] = o;
    } else {
        int j4 = i4 - XQUADS;         // 0 .. WQUADS-1
        int h = j4 >> 6;
        int cq = j4 & 63;
        const float* src = (h < 512) ? (Wre + (size_t)h * 256)
                                     : (Wim + (size_t)(h - 512) * 256);
        float4 v = ((const float4*)src)[cq];
        uint2 o;
        o.x = pack2h(v.x, v.y);
        o.y = pack2h(v.z, v.w);
        ((uint2*)g_wcat)[j4] = o;
    }
}

// ---------------- tensor-core GEMM (monolithic, R14) --------------------------
#define STG  10240
#define BOFF (3 * STG)
#define NIT  (KCAT / 32)   // 8

__device__ __forceinline__ void ldsm_x4(u32 addr, u32& r0, u32& r1,
                                        u32& r2, u32& r3) {
    asm volatile("ldmatrix.sync.aligned.m8n8.x4.shared.b16 {%0,%1,%2,%3}, [%4];"
                 : "=r"(r0), "=r"(r1), "=r"(r2), "=r"(r3) : "r"(addr));
}
__device__ __forceinline__ void mma16816(float* c, const u32* a,
                                         u32 b0, u32 b1) {
    asm volatile(
        "mma.sync.aligned.m16n8k16.row.col.f32.f16.f16.f32 "
        "{%0,%1,%2,%3}, {%4,%5,%6,%7}, {%8,%9}, {%0,%1,%2,%3};"
        : "+f"(c[0]), "+f"(c[1]), "+f"(c[2]), "+f"(c[3])
        : "r"(a[0]), "r"(a[1]), "r"(a[2]), "r"(a[3]), "r"(b0), "r"(b1));
}

__global__ void __launch_bounds__(128) mma_gemm_kernel() {
    extern __shared__ __align__(16) char dsm[];

    int tid  = threadIdx.x;
    int warp = tid >> 5, lane = tid & 31;
    int bm = blockIdx.y << 7, bn = blockIdx.x << 7;
    int wm = (warp & 1) << 6, wn = (warp >> 1) << 6;

    u32 sBase = (u32)__cvta_generic_to_shared(dsm);

    int lr = tid >> 2, lc = (tid & 3) << 3;
    const __half* gA = g_xcat + (size_t)(bm + lr) * KCAT + lc;
    const __half* gB = g_wcat + (size_t)(bn + lr) * KCAT + lc;
    u32 stA = sBase + (u32)(lr * 80 + (tid & 3) * 16);
    u32 stB = stA + BOFF;

    int frow  = lane & 15;
    int fbyte = (lane >> 4) << 4;
    u32 aOff[4], bOff[4];
    #pragma unroll
    for (int i = 0; i < 4; i++)
        aOff[i] = (u32)((wm + i * 16 + frow) * 80 + fbyte);
    #pragma unroll
    for (int j = 0; j < 4; j++)
        bOff[j] = (u32)(BOFF + (wn + j * 16 + frow) * 80 + fbyte);

    float c[4][8][4];
    #pragma unroll
    for (int i = 0; i < 4; i++)
        #pragma unroll
        for (int o = 0; o < 8; o++)
            #pragma unroll
            for (int k = 0; k < 4; k++) c[i][o][k] = 0.f;

    #pragma unroll
    for (int st = 0; st < 2; st++) {
        u32 offs = st * STG;
        int k = st * 32;
        #pragma unroll
        for (int p = 0; p < 4; p++) {
            asm volatile("cp.async.cg.shared.global [%0], [%1], 16;" ::
                "r"(stA + offs + p * 32 * 80), "l"(gA + (size_t)p * 32 * KCAT + k));
            asm volatile("cp.async.cg.shared.global [%0], [%1], 16;" ::
                "r"(stB + offs + p * 32 * 80), "l"(gB + (size_t)p * 32 * KCAT + k));
        }
        asm volatile("cp.async.commit_group;");
    }

    #pragma unroll 1
    for (int it = 0; it < NIT; it++) {
        asm volatile("cp.async.wait_group 1;");
        __syncthreads();
        if (it + 2 < NIT) {
            int st = (it + 2) % 3;
            u32 offs = (u32)(st * STG);
            int k = (it + 2) * 32;
            #pragma unroll
            for (int p = 0; p < 4; p++) {
                asm volatile("cp.async.cg.shared.global [%0], [%1], 16;" ::
                    "r"(stA + offs + p * 32 * 80), "l"(gA + (size_t)p * 32 * KCAT + k));
                asm volatile("cp.async.cg.shared.global [%0], [%1], 16;" ::
                    "r"(stB + offs + p * 32 * 80), "l"(gB + (size_t)p * 32 * KCAT + k));
            }
        }
        asm volatile("cp.async.commit_group;");

        u32 so = sBase + (u32)((it % 3) * STG);
        #pragma unroll
        for (int kk = 0; kk < 2; kk++) {
            u32 a[4][4], b[4][4];
            #pragma unroll
            for (int i = 0; i < 4; i++)
                ldsm_x4(so + aOff[i] + kk * 32, a[i][0], a[i][1], a[i][2], a[i][3]);
            #pragma unroll
            for (int j = 0; j < 4; j++)
                ldsm_x4(so + bOff[j] + kk * 32, b[j][0], b[j][1], b[j][2], b[j][3]);
            #pragma unroll
            for (int i = 0; i < 4; i++)
                #pragma unroll
                for (int o = 0; o < 8; o++) {
                    int t = o >> 1, p = o & 1;
                    mma16816(c[i][o], a[i], b[t][p], b[t][p + 2]);
                }
        }
    }

    int g = lane >> 2, tg = lane & 3;
    #pragma unroll
    for (int i = 0; i < 4; i++) {
        int r0 = bm + wm + i * 16 + g;
        #pragma unroll
        for (int o = 0; o < 8; o++) {
            int cc = bn + wn + o * 8 + tg * 2;
            *(float2*)(g_embP + (size_t)r0 * NCAT + cc)       = make_float2(c[i][o][0], c[i][o][1]);
            *(float2*)(g_embP + (size_t)(r0 + 8) * NCAT + cc) = make_float2(c[i][o][2], c[i][o][3]);
        }
    }
}

// ---------------- urnn: DIF fwd + DIT inv, fused tail ------------------------
__global__ void __launch_bounds__(256) urnn_kernel(const float* __restrict__ hxr,
                                                   const float* __restrict__ hxi,
                                                   const float* __restrict__ beta,
                                                   float2* __restrict__ out) {
    __shared__ float2 buf[4][576];
    __shared__ float2 sred[8];

    int tid = threadIdx.x;
    int sub = tid >> 6;
    int t   = tid & 63;
    int warp = tid >> 5;
    int row = (blockIdx.x << 2) + sub;
    size_t base = (size_t)row * HID;

    float2* b = buf[sub];
    float2 x[8];

    // ===== forward FFT (DIF radix-8): natural input straight from gmem =====
    #pragma unroll
    for (int m = 0; m < 8; m++) {
        int i = t + (m << 6);
        x[m] = cmul(g_d1n[i], make_float2(hxr[base + i], hxi[base + i]));
    }
    dft8<-1>(x);
    #pragma unroll
    for (int m = 1; m < 8; m++) x[m] = cmul(x[m], g_twf[t * m]);
    #pragma unroll
    for (int m = 0; m < 8; m++) b[PAD((m << 6) + t)] = x[m];
    __syncthreads();

    // stage 2
    {
        int m2 = t >> 3, a = t & 7;
        #pragma unroll
        for (int bb = 0; bb < 8; bb++) x[bb] = b[PAD((m2 << 6) + (bb << 3) + a)];
        dft8<-1>(x);
        #pragma unroll
        for (int d = 1; d < 8; d++) x[d] = cmul(x[d], g_twf[(a * d) << 3]);
        #pragma unroll
        for (int d = 0; d < 8; d++) b[PAD((m2 << 6) + (d << 3) + a)] = x[d];
    }
    __syncthreads();

    // stage 3 in registers
    #pragma unroll
    for (int a = 0; a < 8; a++) x[a] = b[PAD((t << 3) + a)];
    dft8<-1>(x);

    // Householder 1
    float2 v[8];
    float2 acc = make_float2(0.f, 0.f);
    #pragma unroll
    for (int c = 0; c < 8; c++) {
        v[c] = g_v1p[(c << 6) + t];
        acc = cadd(acc, cmul(x[c], v[c]));
    }
    #pragma unroll
    for (int o = 16; o; o >>= 1) {
        acc.x += __shfl_xor_sync(0xffffffffu, acc.x, o);
        acc.y += __shfl_xor_sync(0xffffffffu, acc.y, o);
    }
    if ((tid & 31) == 0) sred[warp] = acc;
    __syncthreads();
    {
        float2 s = cadd(sred[sub << 1], sred[(sub << 1) | 1]);
        float2 m = make_float2(2.f * s.x, 2.f * s.y);
        #pragma unroll
        for (int c = 0; c < 8; c++)
            x[c] = csub(x[c], cmul(m, make_float2(v[c].x, -v[c].y)));
    }
    // safe: all reads of b completed before the sred barrier above
    {
        int lo = ((t & 7) << 3) + (t >> 3);
        #pragma unroll
        for (int c = 0; c < 8; c++) b[PAD((c << 6) + lo)] = x[c];
    }
    __syncthreads();

    // ===== inverse FFT (DIT); 1/512 is folded into g_d2r8 =====
    #pragma unroll
    for (int k = 0; k < 8; k++) {
        int i = (t << 3) + k;
        x[k] = cmul(g_d2r8[i], b[g_pp8[i]]);
    }
    dft8<1>(x);
    __syncthreads();
    #pragma unroll
    for (int k = 0; k < 8; k++) b[PAD((t << 3) + k)] = x[k];
    __syncthreads();

    fft_stage1<1>(b, t, g_twi);
    __syncthreads();

    #pragma unroll
    for (int k = 0; k < 8; k++) x[k] = b[PAD(t + (k << 6))];
    #pragma unroll
    for (int k = 1; k < 8; k++) x[k] = cmul(x[k], g_twi[t * k]);
    dft8<1>(x);

    // Householder 2
    acc = make_float2(0.f, 0.f);
    #pragma unroll
    for (int k = 0; k < 8; k++) {
        v[k] = g_v2[t + (k << 6)];
        acc = cadd(acc, cmul(x[k], v[k]));
    }
    #pragma unroll
    for (int o = 16; o; o >>= 1) {
        acc.x += __shfl_xor_sync(0xffffffffu, acc.x, o);
        acc.y += __shfl_xor_sync(0xffffffffu, acc.y, o);
    }
    if ((tid & 31) == 0) sred[warp] = acc;
    __syncthreads();
    float2 s2 = cadd(sred[sub << 1], sred[(sub << 1) | 1]);
    float2 m2 = make_float2(2.f * s2.x, 2.f * s2.y);

    const float* embRe = g_embP + (size_t)row * NCAT;
    const float* embIm = embRe + 512;

    #pragma unroll
    for (int k = 0; k < 8; k++) {
        int e = t + (k << 6);
        float2 h = csub(x[k], cmul(m2, make_float2(v[k].x, -v[k].y)));
        h = cmul(g_d3[e], h);
        h.x += embRe[e]; h.y += embIm[e];
        float d = h.x * h.x + h.y * h.y;
        float2 res;
        if (d > 0.f) {
            float rs  = rsqrtf(d);
            float mag = d * rs;
            float r   = mag + beta[e];
            r = r > 0.f ? r : 0.f;
            float sc = r * rs;
            res = make_float2(sc * h.x, sc * h.y);
        } else {
            float r = beta[e] > 0.f ? beta[e] : 0.f;
            res = make_float2(r, 0.f);
        }
        out[base + e] = res;
    }
}

// ---------------- launch (R14 schedule) ---------------------------------------
extern "C" void kernel_launch(void* const* d_in, const int* in_sizes, int n_in,
                              void* d_out, int out_size) {
    const float* x      = (const float*)d_in[0];
    const float* hxr    = (const float*)d_in[1];
    const float* hxi    = (const float*)d_in[2];
    const float* angles = (const float*)d_in[3];
    const float* rre    = (const float*)d_in[4];
    const float* rim    = (const float*)d_in[5];
    const float* Wre    = (const float*)d_in[6];
    const float* Wim    = (const float*)d_in[7];
    const float* beta   = (const float*)d_in[8];
    const int*   perm   = (const int*)d_in[9];
    float2* out = (float2*)d_out;

    static cudaStream_t s2 = 0;
    static cudaEvent_t ev0 = 0, evG = 0;
    static int inited = 0;
    if (!inited) {
        cudaFuncSetAttribute(mma_gemm_kernel,
                             cudaFuncAttributeMaxDynamicSharedMemorySize, 6 * STG);
        cudaStreamCreateWithFlags(&s2, cudaStreamNonBlocking);
        cudaEventCreateWithFlags(&ev0, cudaEventDisableTiming);
        cudaEventCreateWithFlags(&evG, cudaEventDisableTiming);
        inited = 1;
    }

    // fork: merged convert + GEMM on s2 (independent of prep)
    cudaEventRecord(ev0, 0);
    cudaStreamWaitEvent(s2, ev0, 0);
    convert_kernel<<<(XQUADS + WQUADS) / 256, 256, 0, s2>>>(x, Wre, Wim);
    dim3 gg(NCAT / 128, B_ROWS / 128);
    mma_gemm_kernel<<<gg, 128, 6 * STG, s2>>>();
    cudaEventRecord(evG, s2);

    // main stream: prep (tiny), then join and run urnn
    prep_kernel<<<1, 512>>>(angles, rre, rim, perm);
    cudaStreamWaitEvent(0, evG, 0);
    urnn_kernel<<<B_ROWS / 4, 256>>>(hxr, hxi, beta, out);
}